// round 2
// baseline (speedup 1.0000x reference)
#include <cuda_runtime.h>

// RawISPProcessing: demosaic (2x bilinear; reference's flips cancel exactly) +
// fused channel-flip/awb/ccm 3x3 matrix (incl. the *2) + gamma, for pred and gt.
//
// R2: W-coarsened (4 input cols / thread), float4 loads + float4 stores.

#define HIN  512
#define WIN  512
#define PLANE (HIN * WIN)
#define OPLANE (1024 * 1024)

__device__ float g_A[8 * 9];   // fused per-batch matrix

__global__ void prep_mat_kernel(const float* __restrict__ awb,
                                const float* __restrict__ ccm) {
    int t = threadIdx.x;       // 72 threads: 8 batches x 9 entries
    if (t >= 72) return;
    int b = t / 9;
    int r = t % 9;
    int j = r / 3;             // input RGB channel
    int c = r % 3;             // output RGB channel
    const float* Aw = awb + b * 9;
    const float* Cm = ccm + b * 9;
    float s = 0.0f;
#pragma unroll
    for (int m = 0; m < 3; m++)
        s += Aw[(2 - j) * 3 + m] * Cm[m * 3 + (2 - c)];
    g_A[t] = 2.0f * s;
}

__device__ __forceinline__ float gamma_pow(float v) {
    v = fmaxf(v, 1e-8f);
    float l;
    asm("lg2.approx.f32 %0, %1;" : "=f"(l) : "f"(v));
    l *= 0.45454545454545453f;   // 1/2.2
    float r;
    asm("ex2.approx.f32 %0, %1;" : "=f"(r) : "f"(l));
    return r;
}

// Horizontal 2x bilinear over 4 aligned input cols (c4..c4+3) of one row.
// le/re: at left/right image edge (clamp).
__device__ __forceinline__ void hinterp(const float* __restrict__ p, int row, int c4,
                                        bool le, bool re, float hx[8]) {
    float4 m = *(const float4*)(p + row + c4);
    float L = le ? m.x : __ldg(p + row + c4 - 1);
    float R = re ? m.w : __ldg(p + row + c4 + 4);
    float t0 = L, t1 = m.x, t2 = m.y, t3 = m.z, t4 = m.w, t5 = R;
    hx[0] = 0.25f * t0 + 0.75f * t1;
    hx[1] = 0.75f * t1 + 0.25f * t2;
    hx[2] = 0.25f * t1 + 0.75f * t2;
    hx[3] = 0.75f * t2 + 0.25f * t3;
    hx[4] = 0.25f * t2 + 0.75f * t3;
    hx[5] = 0.75f * t3 + 0.25f * t4;
    hx[6] = 0.25f * t3 + 0.75f * t4;
    hx[7] = 0.75f * t4 + 0.25f * t5;
}

// 2x bilinear upsample of one plane over a 1x4 input strip -> 2x8 outputs.
__device__ __forceinline__ void up2strip(const float* __restrict__ p,
                                         int hm, int h0, int hp, int c4,
                                         bool le, bool re,
                                         float o0[8], float o1[8]) {
    float a[8], b[8], c[8];
    hinterp(p, hm, c4, le, re, a);
    hinterp(p, h0, c4, le, re, b);
    hinterp(p, hp, c4, le, re, c);
#pragma unroll
    for (int j = 0; j < 8; j++) {
        o0[j] = 0.25f * a[j] + 0.75f * b[j];
        o1[j] = 0.75f * b[j] + 0.25f * c[j];
    }
}

__global__ __launch_bounds__(128)
void isp_kernel(const float* __restrict__ pred,
                const float* __restrict__ gt,
                float* __restrict__ out) {
    const int w4 = blockIdx.x * 32 + threadIdx.x;   // strip index 0..127
    const int c4 = w4 * 4;                          // input col base
    const int h  = blockIdx.y * 4 + threadIdx.y;    // input row 0..511
    const int z  = blockIdx.z;                      // 0..15
    const int which = z >> 3;                       // 0 = pred->x, 1 = gt->y
    const int b  = z & 7;

    const float* __restrict__ img =
        (which ? gt : pred) + (size_t)b * (4 * PLANE);

    float A[9];
#pragma unroll
    for (int i = 0; i < 9; i++) A[i] = g_A[b * 9 + i];

    const int hm = max(h - 1, 0) * WIN;
    const int h0 = h * WIN;
    const int hp = min(h + 1, HIN - 1) * WIN;
    const bool le = (c4 == 0);
    const bool re = (c4 == WIN - 4);

    float R0[8], R1[8], G0[8], G1[8], B0[8], B1[8];
    {
        float gr0[8], gr1[8], gb0[8], gb1[8];
        up2strip(img + 1 * PLANE, hm, h0, hp, c4, le, re, gr0, gr1);
        up2strip(img + 2 * PLANE, hm, h0, hp, c4, le, re, gb0, gb1);
        // green mosaic: out-row even: even col = avg, odd col = gr
        //               out-row odd : even col = gb,  odd col = avg
#pragma unroll
        for (int j = 0; j < 4; j++) {
            G0[2 * j]     = 0.5f * (gr0[2 * j] + gb0[2 * j]);
            G0[2 * j + 1] = gr0[2 * j + 1];
            G1[2 * j]     = gb1[2 * j];
            G1[2 * j + 1] = 0.5f * (gr1[2 * j + 1] + gb1[2 * j + 1]);
        }
    }
    up2strip(img + 0 * PLANE, hm, h0, hp, c4, le, re, R0, R1);
    up2strip(img + 3 * PLANE, hm, h0, hp, c4, le, re, B0, B1);

    const size_t obase = ((size_t)which * 8 + b) * (3 * (size_t)OPLANE);
    const int ocol = 8 * w4;

#pragma unroll
    for (int c = 0; c < 3; c++) {
        const float a0 = A[c], a1 = A[3 + c], a2 = A[6 + c];
        float v0[8], v1[8];
#pragma unroll
        for (int j = 0; j < 8; j++) {
            v0[j] = gamma_pow(fmaf(a0, R0[j], fmaf(a1, G0[j], a2 * B0[j])));
            v1[j] = gamma_pow(fmaf(a0, R1[j], fmaf(a1, G1[j], a2 * B1[j])));
        }
        float* row0 = out + obase + (size_t)c * OPLANE + (size_t)(2 * h) * 1024 + ocol;
        float* row1 = row0 + 1024;
        *(float4*)(row0)     = make_float4(v0[0], v0[1], v0[2], v0[3]);
        *(float4*)(row0 + 4) = make_float4(v0[4], v0[5], v0[6], v0[7]);
        *(float4*)(row1)     = make_float4(v1[0], v1[1], v1[2], v1[3]);
        *(float4*)(row1 + 4) = make_float4(v1[4], v1[5], v1[6], v1[7]);
    }
}

extern "C" void kernel_launch(void* const* d_in, const int* in_sizes, int n_in,
                              void* d_out, int out_size) {
    const float* pred = (const float*)d_in[0];
    const float* gt   = (const float*)d_in[1];
    const float* awb  = (const float*)d_in[2];
    const float* ccm  = (const float*)d_in[3];
    // d_in[4] = rgb_gain: unused by the reference

    prep_mat_kernel<<<1, 72>>>(awb, ccm);

    dim3 blk(32, 4);
    dim3 grd(4, 128, 16);   // 128 strips x 512 rows x (2 images * 8 batches)
    isp_kernel<<<grd, blk>>>(pred, gt, (float*)d_out);
}

// round 3
// speedup vs baseline: 1.2333x; 1.2333x over previous
#include <cuda_runtime.h>

// RawISPProcessing: demosaic (2x bilinear; reference's flips cancel exactly) +
// fused channel-flip/awb/ccm 3x3 matrix (incl. the *2) + gamma, for pred and gt.
//
// R3: back to 1-thread-per-input-pixel (R1 shape, occ ~66%), with immediate-
// offset plane addressing, FFMA-imm lerps, and green dead-code trim.

#define HIN  512
#define WIN  512
#define PLANE (HIN * WIN)
#define OPLANE (1024 * 1024)

__device__ float g_A[8 * 9];   // fused per-batch matrix

__global__ void prep_mat_kernel(const float* __restrict__ awb,
                                const float* __restrict__ ccm) {
    int t = threadIdx.x;       // 72 threads: 8 batches x 9 entries
    if (t >= 72) return;
    int b = t / 9;
    int r = t % 9;
    int j = r / 3;             // input RGB channel
    int c = r % 3;             // output RGB channel
    const float* Aw = awb + b * 9;
    const float* Cm = ccm + b * 9;
    float s = 0.0f;
#pragma unroll
    for (int m = 0; m < 3; m++)
        s += Aw[(2 - j) * 3 + m] * Cm[m * 3 + (2 - c)];
    g_A[t] = 2.0f * s;
}

// 0.25*a + 0.75*b, in FADD + FFMA-imm form (src1-immediate FFMA has rt=1)
__device__ __forceinline__ float lerp14(float a, float b) {
    return fmaf(0.25f, a - b, b);
}

__device__ __forceinline__ float gamma_pow(float v) {
    v = fmaxf(v, 1e-8f);
    float l;
    asm("lg2.approx.f32 %0, %1;" : "=f"(l) : "f"(v));
    l *= 0.45454545454545453f;   // 1/2.2
    float r;
    asm("ex2.approx.f32 %0, %1;" : "=f"(r) : "f"(l));
    return r;
}

// 2x bilinear 2x2 block for plane K (compile-time), loads via immediate
// plane offsets off the three shared row pointers. Fully inlined & pure so
// unused lanes are dead-code eliminated (green planes use only 3 of 4).
template <int K>
__device__ __forceinline__ float4 up2x2(const float* __restrict__ pm,
                                        const float* __restrict__ p0,
                                        const float* __restrict__ pp,
                                        int wm, int w, int wp) {
    const int PO = K * PLANE;
    float a00 = pm[PO + wm], a01 = pm[PO + w], a02 = pm[PO + wp];
    float a10 = p0[PO + wm], a11 = p0[PO + w], a12 = p0[PO + wp];
    float a20 = pp[PO + wm], a21 = pp[PO + w], a22 = pp[PO + wp];
    float r0x0 = lerp14(a00, a01), r0x1 = lerp14(a02, a01);
    float r1x0 = lerp14(a10, a11), r1x1 = lerp14(a12, a11);
    float r2x0 = lerp14(a20, a21), r2x1 = lerp14(a22, a21);
    float4 u;
    u.x = lerp14(r0x0, r1x0);   // (dy0,dx0)
    u.y = lerp14(r0x1, r1x1);   // (dy0,dx1)
    u.z = lerp14(r2x0, r1x0);   // (dy1,dx0)
    u.w = lerp14(r2x1, r1x1);   // (dy1,dx1)
    return u;
}

__global__ __launch_bounds__(256)
void isp_kernel(const float* __restrict__ pred,
                const float* __restrict__ gt,
                float* __restrict__ out) {
    const int w = blockIdx.x * 32 + threadIdx.x;   // input col 0..511
    const int h = blockIdx.y * 8 + threadIdx.y;    // input row 0..511
    const int z = blockIdx.z;                      // which*8 + b
    const int b = z & 7;

    const float* __restrict__ img =
        ((z >> 3) ? gt : pred) + (size_t)b * (4 * PLANE);

    // three row pointers shared by all four planes
    const float* pm = img + max(h - 1, 0) * WIN;
    const float* p0 = img + h * WIN;
    const float* pp = img + min(h + 1, HIN - 1) * WIN;
    const int wm = max(w - 1, 0);
    const int wp = min(w + 1, WIN - 1);

    float4 R  = up2x2<0>(pm, p0, pp, wm, w, wp);
    float4 GR = up2x2<1>(pm, p0, pp, wm, w, wp);
    float4 GB = up2x2<2>(pm, p0, pp, wm, w, wp);
    float4 Bl = up2x2<3>(pm, p0, pp, wm, w, wp);

    // green mosaic: (ee),(oo) = avg(gr,gb); (eo) = gr; (oe) = gb
    // GR.z and GB.y are never used -> their lerps/loads are DCE'd.
    float G00 = fmaf(0.5f, GR.x - GB.x, GB.x);
    float G01 = GR.y;
    float G10 = GB.z;
    float G11 = fmaf(0.5f, GR.w - GB.w, GB.w);

    float A[9];
#pragma unroll
    for (int i = 0; i < 9; i++) A[i] = g_A[b * 9 + i];

    float r4[4] = {R.x, R.y, R.z, R.w};
    float g4[4] = {G00, G01, G10, G11};
    float b4[4] = {Bl.x, Bl.y, Bl.z, Bl.w};

    // one output base pointer; channel & row offsets become immediates
    float* po = out + (size_t)z * (3 * (size_t)OPLANE)
                    + (size_t)(2 * h) * 1024 + 2 * w;

#pragma unroll
    for (int c = 0; c < 3; c++) {
        const float a0 = A[c], a1 = A[3 + c], a2 = A[6 + c];
        float v00 = gamma_pow(fmaf(a0, r4[0], fmaf(a1, g4[0], a2 * b4[0])));
        float v01 = gamma_pow(fmaf(a0, r4[1], fmaf(a1, g4[1], a2 * b4[1])));
        float v10 = gamma_pow(fmaf(a0, r4[2], fmaf(a1, g4[2], a2 * b4[2])));
        float v11 = gamma_pow(fmaf(a0, r4[3], fmaf(a1, g4[3], a2 * b4[3])));
        *(float2*)(po + c * OPLANE)        = make_float2(v00, v01);
        *(float2*)(po + c * OPLANE + 1024) = make_float2(v10, v11);
    }
}

extern "C" void kernel_launch(void* const* d_in, const int* in_sizes, int n_in,
                              void* d_out, int out_size) {
    const float* pred = (const float*)d_in[0];
    const float* gt   = (const float*)d_in[1];
    const float* awb  = (const float*)d_in[2];
    const float* ccm  = (const float*)d_in[3];
    // d_in[4] = rgb_gain: unused by the reference

    prep_mat_kernel<<<1, 72>>>(awb, ccm);

    dim3 blk(32, 8);
    dim3 grd(16, 64, 16);
    isp_kernel<<<grd, blk>>>(pred, gt, (float*)d_out);
}

// round 4
// speedup vs baseline: 1.4506x; 1.1762x over previous
#include <cuda_runtime.h>

// RawISPProcessing: demosaic (2x bilinear; reference's flips cancel exactly) +
// fused channel-flip/awb/ccm 3x3 matrix (incl. the *2) + gamma, for pred & gt.
//
// R4: vertical rolling window — each thread owns an 8-row column strip.
// Horizontal lerps computed ONCE per input row (vs 3x in R1/R3), loads cut
// ~3x. Fused matrix computed inline (no prep kernel).

#define HIN  512
#define WIN  512
#define PLANE (HIN * WIN)
#define OPLANE (1024 * 1024)
#define R_ROWS 8

// 0.25*a + 0.75*b  (FADD + FFMA-imm form)
__device__ __forceinline__ float lerp14(float a, float b) {
    return fmaf(0.25f, a - b, b);
}

__device__ __forceinline__ float gamma_pow(float v) {
    v = fmaxf(v, 1e-8f);
    float l;
    asm("lg2.approx.f32 %0, %1;" : "=f"(l) : "f"(v));
    l *= 0.45454545454545453f;   // 1/2.2
    float r;
    asm("ex2.approx.f32 %0, %1;" : "=f"(r) : "f"(l));
    return r;
}

// Horizontal lerps of one input row, both output columns, all 4 planes.
struct HL { float r0, r1, gr0, gr1, gb0, gb1, b0, b1; };

__device__ __forceinline__ HL hlerp(const float* __restrict__ img, int row,
                                    int wm, int w, int wp) {
    const float* p = img + row * WIN;
    HL h;
    float a, b, c;
    a = p[wm];             b = p[w];             c = p[wp];
    h.r0 = lerp14(a, b);   h.r1 = lerp14(c, b);
    a = p[PLANE + wm];     b = p[PLANE + w];     c = p[PLANE + wp];
    h.gr0 = lerp14(a, b);  h.gr1 = lerp14(c, b);
    a = p[2 * PLANE + wm]; b = p[2 * PLANE + w]; c = p[2 * PLANE + wp];
    h.gb0 = lerp14(a, b);  h.gb1 = lerp14(c, b);
    a = p[3 * PLANE + wm]; b = p[3 * PLANE + w]; c = p[3 * PLANE + wp];
    h.b0 = lerp14(a, b);   h.b1 = lerp14(c, b);
    return h;
}

// Color matrix + gamma + store for one output row (2 cols x 3 channels).
__device__ __forceinline__ void emit_row(float* __restrict__ po, const float* A,
                                         float r0, float r1, float g0, float g1,
                                         float b0, float b1) {
#pragma unroll
    for (int c = 0; c < 3; c++) {
        float v0 = gamma_pow(fmaf(A[c], r0, fmaf(A[3 + c], g0, A[6 + c] * b0)));
        float v1 = gamma_pow(fmaf(A[c], r1, fmaf(A[3 + c], g1, A[6 + c] * b1)));
        *(float2*)(po + c * OPLANE) = make_float2(v0, v1);
    }
}

// Even output row (2r+2): 0.25*ha + 0.75*hb.  G: even col = avg, odd = gr.
__device__ __forceinline__ void emit_even(float* __restrict__ po, const float* A,
                                          const HL& ha, const HL& hb) {
    float r0 = lerp14(ha.r0, hb.r0),   r1 = lerp14(ha.r1, hb.r1);
    float gr0 = lerp14(ha.gr0, hb.gr0), gr1 = lerp14(ha.gr1, hb.gr1);
    float gb0 = lerp14(ha.gb0, hb.gb0);
    float b0 = lerp14(ha.b0, hb.b0),   b1 = lerp14(ha.b1, hb.b1);
    emit_row(po, A, r0, r1, fmaf(0.5f, gr0 - gb0, gb0), gr1, b0, b1);
}

// Odd output row (2r+1): 0.75*ha + 0.25*hb.  G: even col = gb, odd = avg.
__device__ __forceinline__ void emit_odd(float* __restrict__ po, const float* A,
                                         const HL& ha, const HL& hb) {
    float r0 = lerp14(hb.r0, ha.r0),   r1 = lerp14(hb.r1, ha.r1);
    float gr1 = lerp14(hb.gr1, ha.gr1);
    float gb0 = lerp14(hb.gb0, ha.gb0), gb1 = lerp14(hb.gb1, ha.gb1);
    float b0 = lerp14(hb.b0, ha.b0),   b1 = lerp14(hb.b1, ha.b1);
    emit_row(po, A, r0, r1, gb0, fmaf(0.5f, gr1 - gb1, gb1), b0, b1);
}

__global__ __launch_bounds__(256)
void isp_kernel(const float* __restrict__ pred,
                const float* __restrict__ gt,
                const float* __restrict__ awb,
                const float* __restrict__ ccm,
                float* __restrict__ out) {
    const int w = blockIdx.x * 32 + threadIdx.x;     // input col 0..511
    const int strip = blockIdx.y * 8 + threadIdx.y;  // 0..63
    const int h0 = strip * R_ROWS;
    const int z = blockIdx.z;                        // which*8 + b
    const int b = z & 7;

    const float* __restrict__ img =
        ((z >> 3) ? gt : pred) + (size_t)b * (4 * PLANE);

    // fused matrix: A[j*3+c] = 2 * sum_m awb[b,2-j,m] * ccm[b,m,2-c]
    float A[9];
    {
        const float* Aw = awb + b * 9;
        const float* Cm = ccm + b * 9;
#pragma unroll
        for (int j = 0; j < 3; j++)
#pragma unroll
            for (int c = 0; c < 3; c++) {
                float s = 0.0f;
#pragma unroll
                for (int m = 0; m < 3; m++)
                    s = fmaf(__ldg(Aw + (2 - j) * 3 + m),
                             __ldg(Cm + m * 3 + (2 - c)), s);
                A[j * 3 + c] = 2.0f * s;
            }
    }

    const int wm = max(w - 1, 0);
    const int wp = min(w + 1, WIN - 1);

    float* po = out + (size_t)z * (3 * (size_t)OPLANE)
                    + (size_t)(2 * h0) * 1024 + 2 * w;

    HL ha = hlerp(img, max(h0 - 1, 0), wm, w, wp);
    HL hb = hlerp(img, h0, wm, w, wp);

    // first row of strip: output row 2*h0 (even) from (h0-1, h0)
    emit_even(po, A, ha, hb);
    po += 1024;

#pragma unroll 2
    for (int r = 0; r < R_ROWS - 1; r++) {
        ha = hb;
        hb = hlerp(img, h0 + r + 1, wm, w, wp);
        emit_odd(po, A, ha, hb);          // row 2*(h0+r)+1
        emit_even(po + 1024, A, ha, hb);  // row 2*(h0+r)+2
        po += 2048;
    }

    // last row of strip: output row 2*h0+2R-1 (odd) from (h0+R-1, h0+R)
    ha = hb;
    hb = hlerp(img, min(h0 + R_ROWS, HIN - 1), wm, w, wp);
    emit_odd(po, A, ha, hb);
}

extern "C" void kernel_launch(void* const* d_in, const int* in_sizes, int n_in,
                              void* d_out, int out_size) {
    const float* pred = (const float*)d_in[0];
    const float* gt   = (const float*)d_in[1];
    const float* awb  = (const float*)d_in[2];
    const float* ccm  = (const float*)d_in[3];
    // d_in[4] = rgb_gain: unused by the reference

    dim3 blk(32, 8);
    dim3 grd(16, 8, 16);   // 16 col-groups x 64 strips x (2 images * 8 batches)
    isp_kernel<<<grd, blk>>>(pred, gt, awb, ccm, (float*)d_out);
}